// round 1
// baseline (speedup 1.0000x reference)
#include <cuda_runtime.h>
#include <math.h>

// Problem dims
#define NCAT   1024
#define INDIM  1024
#define HDIM   2048
#define GDIM   (4 * HDIM)      // 8192
#define XDIM   (NCAT + INDIM)  // 2048
#define OUTDIM 32000
#define WOUT_K (NCAT + HDIM)   // 3072

// Scratch (no allocations allowed)
__device__ float g_x[XDIM];
__device__ float g_gates0[GDIM];
__device__ float g_gates1[GDIM];
__device__ float g_h1[HDIM];
__device__ float g_h2[HDIM];
__device__ float g_logits[OUTDIM];

// ---------------------------------------------------------------------------
// concat category + input -> g_x
__global__ void concat_x_kernel(const float* __restrict__ cat,
                                const float* __restrict__ inp) {
    int i = blockIdx.x * blockDim.x + threadIdx.x;
    if (i < NCAT) g_x[i] = cat[i];
    else if (i < XDIM) g_x[i] = inp[i - NCAT];
}

// ---------------------------------------------------------------------------
// gates[r] = dot(W1[r,:], v1) + dot(W2[r,:], v2) + b1[r] + b2[r]
// W1, W2: [GDIM, 2048] row-major. One warp per row, float4 loads.
__global__ void lstm_gates_kernel(const float* __restrict__ W1,
                                  const float* __restrict__ W2,
                                  const float* __restrict__ v1,
                                  const float* __restrict__ v2,
                                  const float* __restrict__ b1,
                                  const float* __restrict__ b2,
                                  float* __restrict__ gates) {
    int warp = (blockIdx.x * blockDim.x + threadIdx.x) >> 5;
    int lane = threadIdx.x & 31;
    if (warp >= GDIM) return;

    const float4* w1 = (const float4*)(W1 + (size_t)warp * 2048);
    const float4* w2 = (const float4*)(W2 + (size_t)warp * 2048);
    const float4* x1 = (const float4*)v1;  // 512 float4
    const float4* x2 = (const float4*)v2;

    float acc = 0.f;
#pragma unroll
    for (int i = 0; i < 16; i++) {
        float4 a = w1[lane + 32 * i];
        float4 b = x1[lane + 32 * i];
        acc += a.x * b.x + a.y * b.y + a.z * b.z + a.w * b.w;
    }
#pragma unroll
    for (int i = 0; i < 16; i++) {
        float4 a = w2[lane + 32 * i];
        float4 b = x2[lane + 32 * i];
        acc += a.x * b.x + a.y * b.y + a.z * b.z + a.w * b.w;
    }
#pragma unroll
    for (int off = 16; off; off >>= 1)
        acc += __shfl_down_sync(0xffffffffu, acc, off);
    if (lane == 0) gates[warp] = acc + b1[warp] + b2[warp];
}

// ---------------------------------------------------------------------------
// LSTM cell nonlinearity. PyTorch gate order i,f,g,o in blocks of HDIM.
// Writes h to scratch (for next matvec) and h,c to the output buffer slots.
__device__ __forceinline__ float sigmoidf_(float x) {
    return 1.0f / (1.0f + expf(-x));
}

__global__ void lstm_cell_kernel(const float* __restrict__ gates,
                                 const float* __restrict__ c_prev,
                                 float* __restrict__ h_scratch,
                                 float* __restrict__ out_h,
                                 float* __restrict__ out_c) {
    int j = blockIdx.x * blockDim.x + threadIdx.x;
    if (j >= HDIM) return;
    float ig = sigmoidf_(gates[j]);
    float fg = sigmoidf_(gates[HDIM + j]);
    float gg = tanhf(gates[2 * HDIM + j]);
    float og = sigmoidf_(gates[3 * HDIM + j]);
    float c_new = fg * c_prev[j] + ig * gg;
    float h_new = og * tanhf(c_new);
    h_scratch[j] = h_new;
    out_h[j] = h_new;
    out_c[j] = c_new;
}

// ---------------------------------------------------------------------------
// logits[r] = dot(w_out[r, 0:1024], category) + dot(w_out[r, 1024:3072], h2) + b[r]
// One warp per row; row length 3072 floats = 768 float4.
__global__ void out_matvec_kernel(const float* __restrict__ W,
                                  const float* __restrict__ cat,
                                  const float* __restrict__ b) {
    int warp = (blockIdx.x * blockDim.x + threadIdx.x) >> 5;
    int lane = threadIdx.x & 31;
    if (warp >= OUTDIM) return;

    const float4* w  = (const float4*)(W + (size_t)warp * WOUT_K);
    const float4* vc = (const float4*)cat;   // 256 float4
    const float4* vh = (const float4*)g_h2;  // 512 float4

    float acc = 0.f;
#pragma unroll
    for (int i = 0; i < 8; i++) {
        float4 a = w[lane + 32 * i];
        float4 x = vc[lane + 32 * i];
        acc += a.x * x.x + a.y * x.y + a.z * x.z + a.w * x.w;
    }
    const float4* w2 = w + 256;
#pragma unroll
    for (int i = 0; i < 16; i++) {
        float4 a = w2[lane + 32 * i];
        float4 x = vh[lane + 32 * i];
        acc += a.x * x.x + a.y * x.y + a.z * x.z + a.w * x.w;
    }
#pragma unroll
    for (int off = 16; off; off >>= 1)
        acc += __shfl_down_sync(0xffffffffu, acc, off);
    if (lane == 0) g_logits[warp] = acc + b[warp];
}

// ---------------------------------------------------------------------------
// log_softmax over 32000 logits; single block.
__global__ void log_softmax_kernel(float* __restrict__ out) {
    __shared__ float red[32];
    int tid = threadIdx.x;
    int lane = tid & 31;
    int wid = tid >> 5;
    int nwarps = blockDim.x >> 5;

    // max reduce
    float m = -INFINITY;
    for (int i = tid; i < OUTDIM; i += blockDim.x) m = fmaxf(m, g_logits[i]);
#pragma unroll
    for (int off = 16; off; off >>= 1)
        m = fmaxf(m, __shfl_xor_sync(0xffffffffu, m, off));
    if (lane == 0) red[wid] = m;
    __syncthreads();
    if (wid == 0) {
        float v = (lane < nwarps) ? red[lane] : -INFINITY;
#pragma unroll
        for (int off = 16; off; off >>= 1)
            v = fmaxf(v, __shfl_xor_sync(0xffffffffu, v, off));
        if (lane == 0) red[0] = v;
    }
    __syncthreads();
    m = red[0];
    __syncthreads();

    // sum-exp reduce
    float s = 0.f;
    for (int i = tid; i < OUTDIM; i += blockDim.x) s += expf(g_logits[i] - m);
#pragma unroll
    for (int off = 16; off; off >>= 1)
        s += __shfl_xor_sync(0xffffffffu, s, off);
    if (lane == 0) red[wid] = s;
    __syncthreads();
    if (wid == 0) {
        float v = (lane < nwarps) ? red[lane] : 0.f;
#pragma unroll
        for (int off = 16; off; off >>= 1)
            v += __shfl_xor_sync(0xffffffffu, v, off);
        if (lane == 0) red[0] = v;
    }
    __syncthreads();
    float lse = m + logf(red[0]);

    for (int i = tid; i < OUTDIM; i += blockDim.x)
        out[i] = g_logits[i] - lse;
}

// ---------------------------------------------------------------------------
extern "C" void kernel_launch(void* const* d_in, const int* in_sizes, int n_in,
                              void* d_out, int out_size) {
    const float* category = (const float*)d_in[0];   // [1,1024]
    const float* input    = (const float*)d_in[1];   // [1,1024]
    const float* hidden   = (const float*)d_in[2];   // [2,1,2048]
    const float* cell     = (const float*)d_in[3];   // [2,1,2048]
    const float* w_ih_l0  = (const float*)d_in[4];   // [8192,2048]
    const float* w_hh_l0  = (const float*)d_in[5];   // [8192,2048]
    const float* b_ih_l0  = (const float*)d_in[6];   // [8192]
    const float* b_hh_l0  = (const float*)d_in[7];
    const float* w_ih_l1  = (const float*)d_in[8];   // [8192,2048]
    const float* w_hh_l1  = (const float*)d_in[9];
    const float* b_ih_l1  = (const float*)d_in[10];
    const float* b_hh_l1  = (const float*)d_in[11];
    const float* w_out    = (const float*)d_in[12];  // [32000,3072]
    const float* b_out    = (const float*)d_in[13];

    float* out = (float*)d_out;
    // layout: logp [32000], new_hidden [2*2048], new_cell [2*2048]
    float* out_logp = out;
    float* out_h1 = out + OUTDIM;
    float* out_h2 = out + OUTDIM + HDIM;
    float* out_c1 = out + OUTDIM + 2 * HDIM;
    float* out_c2 = out + OUTDIM + 3 * HDIM;

    // device-symbol scratch addresses
    float *p_x, *p_g0, *p_g1, *p_h1, *p_h2;
    cudaGetSymbolAddress((void**)&p_x,  g_x);
    cudaGetSymbolAddress((void**)&p_g0, g_gates0);
    cudaGetSymbolAddress((void**)&p_g1, g_gates1);
    cudaGetSymbolAddress((void**)&p_h1, g_h1);
    cudaGetSymbolAddress((void**)&p_h2, g_h2);

    // 1) concat x = [category, input]
    concat_x_kernel<<<(XDIM + 255) / 256, 256>>>(category, input);

    // 2) layer0 gates: 8192 rows, warp/row, 8 warps/block
    lstm_gates_kernel<<<GDIM / 8, 256>>>(w_ih_l0, w_hh_l0, p_x, hidden,
                                         b_ih_l0, b_hh_l0, p_g0);

    // 3) layer0 cell
    lstm_cell_kernel<<<HDIM / 256, 256>>>(p_g0, cell, p_h1, out_h1, out_c1);

    // 4) layer1 gates: input = h1, recurrent = hidden[1]
    lstm_gates_kernel<<<GDIM / 8, 256>>>(w_ih_l1, w_hh_l1, p_h1, hidden + HDIM,
                                         b_ih_l1, b_hh_l1, p_g1);

    // 5) layer1 cell
    lstm_cell_kernel<<<HDIM / 256, 256>>>(p_g1, cell + HDIM, p_h2, out_h2, out_c2);

    // 6) output matvec: 32000 rows, warp/row
    out_matvec_kernel<<<(OUTDIM + 7) / 8, 256>>>(w_out, category, b_out);

    // 7) log_softmax
    log_softmax_kernel<<<1, 1024>>>(out_logp);
}

// round 2
// speedup vs baseline: 1.1660x; 1.1660x over previous
#include <cuda_runtime.h>
#include <math.h>

// Problem dims
#define NCAT   1024
#define INDIM  1024
#define HDIM   2048
#define GDIM   (4 * HDIM)      // 8192
#define OUTDIM 32000
#define WOUT_K (NCAT + HDIM)   // 3072

// Scratch (no allocations allowed)
__device__ float g_gates0[GDIM];
__device__ float g_gates1[GDIM];   // holds partial (w_hh_l1@h0_1 + biases) after K1
__device__ float g_h1[HDIM];
__device__ float g_h2[HDIM];
__device__ float g_logits[OUTDIM]; // holds partial (w_out_cat@cat + b_out) after K1

__device__ __forceinline__ float f4dot(float4 a, float4 b) {
    return a.x * b.x + a.y * b.y + a.z * b.z + a.w * b.w;
}
__device__ __forceinline__ float warp_reduce(float acc) {
#pragma unroll
    for (int off = 16; off; off >>= 1)
        acc += __shfl_down_sync(0xffffffffu, acc, off);
    return acc;
}

// ---------------------------------------------------------------------------
// K1: all input-only matvecs fused.
//   warps [0, 8192):          g_gates0[r] = w_ih_l0[r]@[cat,inp] + w_hh_l0[r]@h0_0 + b
//   warps [8192, 16384):      g_gates1[r] = w_hh_l1[r]@h0_1 + b_ih_l1[r] + b_hh_l1[r]
//   warps [16384, 48384):     g_logits[r] = w_out[r, 0:1024]@cat + b_out[r]
__global__ void k1_input_matvecs(
    const float* __restrict__ cat, const float* __restrict__ inp,
    const float* __restrict__ hidden,
    const float* __restrict__ w_ih_l0, const float* __restrict__ w_hh_l0,
    const float* __restrict__ b_ih_l0, const float* __restrict__ b_hh_l0,
    const float* __restrict__ w_hh_l1,
    const float* __restrict__ b_ih_l1, const float* __restrict__ b_hh_l1,
    const float* __restrict__ w_out, const float* __restrict__ b_out)
{
    int warp = (blockIdx.x * blockDim.x + threadIdx.x) >> 5;
    int lane = threadIdx.x & 31;

    if (warp < GDIM) {
        int r = warp;
        const float4* w1 = (const float4*)(w_ih_l0 + (size_t)r * 2048);
        const float4* w2 = (const float4*)(w_hh_l0 + (size_t)r * 2048);
        const float4* vc = (const float4*)cat;      // 256 float4
        const float4* vi = (const float4*)inp;      // 256 float4
        const float4* vh = (const float4*)hidden;   // h0 layer0: 512 float4
        float acc = 0.f;
#pragma unroll
        for (int i = 0; i < 8; i++)
            acc += f4dot(__ldcs(&w1[lane + 32 * i]), vc[lane + 32 * i]);
#pragma unroll
        for (int i = 0; i < 8; i++)
            acc += f4dot(__ldcs(&w1[256 + lane + 32 * i]), vi[lane + 32 * i]);
#pragma unroll
        for (int i = 0; i < 16; i++)
            acc += f4dot(__ldcs(&w2[lane + 32 * i]), vh[lane + 32 * i]);
        acc = warp_reduce(acc);
        if (lane == 0) g_gates0[r] = acc + b_ih_l0[r] + b_hh_l0[r];
    } else if (warp < 2 * GDIM) {
        int r = warp - GDIM;
        const float4* w  = (const float4*)(w_hh_l1 + (size_t)r * 2048);
        const float4* vh = (const float4*)(hidden + HDIM);  // h0 layer1
        float acc = 0.f;
#pragma unroll
        for (int i = 0; i < 16; i++)
            acc += f4dot(__ldcs(&w[lane + 32 * i]), vh[lane + 32 * i]);
        acc = warp_reduce(acc);
        if (lane == 0) g_gates1[r] = acc + b_ih_l1[r] + b_hh_l1[r];
    } else {
        int r = warp - 2 * GDIM;
        if (r >= OUTDIM) return;
        const float4* w  = (const float4*)(w_out + (size_t)r * WOUT_K);
        const float4* vc = (const float4*)cat;
        float acc = 0.f;
#pragma unroll
        for (int i = 0; i < 8; i++)
            acc += f4dot(__ldcs(&w[lane + 32 * i]), vc[lane + 32 * i]);
        acc = warp_reduce(acc);
        if (lane == 0) g_logits[r] = acc + b_out[r];
    }
}

// ---------------------------------------------------------------------------
// K2: g_gates1[r] += w_ih_l1[r] @ h1
__global__ void k2_l1_ih(const float* __restrict__ w_ih_l1) {
    int warp = (blockIdx.x * blockDim.x + threadIdx.x) >> 5;
    int lane = threadIdx.x & 31;
    if (warp >= GDIM) return;
    const float4* w  = (const float4*)(w_ih_l1 + (size_t)warp * 2048);
    const float4* vh = (const float4*)g_h1;
    float acc = 0.f;
#pragma unroll
    for (int i = 0; i < 16; i++)
        acc += f4dot(__ldcs(&w[lane + 32 * i]), vh[lane + 32 * i]);
    acc = warp_reduce(acc);
    if (lane == 0) g_gates1[warp] += acc;
}

// ---------------------------------------------------------------------------
// K3: g_logits[r] += w_out[r, 1024:3072] @ h2
__global__ void k3_out_h(const float* __restrict__ w_out) {
    int warp = (blockIdx.x * blockDim.x + threadIdx.x) >> 5;
    int lane = threadIdx.x & 31;
    if (warp >= OUTDIM) return;
    const float4* w  = (const float4*)(w_out + (size_t)warp * WOUT_K + NCAT);
    const float4* vh = (const float4*)g_h2;
    float acc = 0.f;
#pragma unroll
    for (int i = 0; i < 16; i++)
        acc += f4dot(__ldcs(&w[lane + 32 * i]), vh[lane + 32 * i]);
    acc = warp_reduce(acc);
    if (lane == 0) g_logits[warp] += acc;
}

// ---------------------------------------------------------------------------
__device__ __forceinline__ float sigmoidf_(float x) {
    return 1.0f / (1.0f + expf(-x));
}

__global__ void lstm_cell_kernel(const float* __restrict__ gates,
                                 const float* __restrict__ c_prev,
                                 float* __restrict__ h_scratch,
                                 float* __restrict__ out_h,
                                 float* __restrict__ out_c) {
    int j = blockIdx.x * blockDim.x + threadIdx.x;
    if (j >= HDIM) return;
    float ig = sigmoidf_(gates[j]);
    float fg = sigmoidf_(gates[HDIM + j]);
    float gg = tanhf(gates[2 * HDIM + j]);
    float og = sigmoidf_(gates[3 * HDIM + j]);
    float c_new = fg * c_prev[j] + ig * gg;
    float h_new = og * tanhf(c_new);
    h_scratch[j] = h_new;
    out_h[j] = h_new;
    out_c[j] = c_new;
}

// ---------------------------------------------------------------------------
// log_softmax over 32000 logits; single block.
__global__ void log_softmax_kernel(float* __restrict__ out) {
    __shared__ float red[32];
    int tid = threadIdx.x;
    int lane = tid & 31;
    int wid = tid >> 5;
    int nwarps = blockDim.x >> 5;

    float m = -INFINITY;
    for (int i = tid; i < OUTDIM; i += blockDim.x) m = fmaxf(m, g_logits[i]);
#pragma unroll
    for (int off = 16; off; off >>= 1)
        m = fmaxf(m, __shfl_xor_sync(0xffffffffu, m, off));
    if (lane == 0) red[wid] = m;
    __syncthreads();
    if (wid == 0) {
        float v = (lane < nwarps) ? red[lane] : -INFINITY;
#pragma unroll
        for (int off = 16; off; off >>= 1)
            v = fmaxf(v, __shfl_xor_sync(0xffffffffu, v, off));
        if (lane == 0) red[0] = v;
    }
    __syncthreads();
    m = red[0];
    __syncthreads();

    float s = 0.f;
    for (int i = tid; i < OUTDIM; i += blockDim.x) s += expf(g_logits[i] - m);
#pragma unroll
    for (int off = 16; off; off >>= 1)
        s += __shfl_xor_sync(0xffffffffu, s, off);
    if (lane == 0) red[wid] = s;
    __syncthreads();
    if (wid == 0) {
        float v = (lane < nwarps) ? red[lane] : 0.f;
#pragma unroll
        for (int off = 16; off; off >>= 1)
            v += __shfl_xor_sync(0xffffffffu, v, off);
        if (lane == 0) red[0] = v;
    }
    __syncthreads();
    float lse = m + logf(red[0]);

    for (int i = tid; i < OUTDIM; i += blockDim.x)
        out[i] = g_logits[i] - lse;
}

// ---------------------------------------------------------------------------
extern "C" void kernel_launch(void* const* d_in, const int* in_sizes, int n_in,
                              void* d_out, int out_size) {
    const float* category = (const float*)d_in[0];
    const float* input    = (const float*)d_in[1];
    const float* hidden   = (const float*)d_in[2];
    const float* cell     = (const float*)d_in[3];
    const float* w_ih_l0  = (const float*)d_in[4];
    const float* w_hh_l0  = (const float*)d_in[5];
    const float* b_ih_l0  = (const float*)d_in[6];
    const float* b_hh_l0  = (const float*)d_in[7];
    const float* w_ih_l1  = (const float*)d_in[8];
    const float* w_hh_l1  = (const float*)d_in[9];
    const float* b_ih_l1  = (const float*)d_in[10];
    const float* b_hh_l1  = (const float*)d_in[11];
    const float* w_out    = (const float*)d_in[12];
    const float* b_out    = (const float*)d_in[13];

    float* out = (float*)d_out;
    float* out_logp = out;
    float* out_h1 = out + OUTDIM;
    float* out_h2 = out + OUTDIM + HDIM;
    float* out_c1 = out + OUTDIM + 2 * HDIM;
    float* out_c2 = out + OUTDIM + 3 * HDIM;

    float *p_g0, *p_g1, *p_h1, *p_h2;
    cudaGetSymbolAddress((void**)&p_g0, g_gates0);
    cudaGetSymbolAddress((void**)&p_g1, g_gates1);
    cudaGetSymbolAddress((void**)&p_h1, g_h1);
    cudaGetSymbolAddress((void**)&p_h2, g_h2);

    // K1: all input-only matvecs (332 MB of weights) in one kernel.
    // 48384 warps = 16384 (gates) + 32000 (logits-cat); 8 warps/block.
    k1_input_matvecs<<<48384 / 8, 256>>>(
        category, input, hidden,
        w_ih_l0, w_hh_l0, b_ih_l0, b_hh_l0,
        w_hh_l1, b_ih_l1, b_hh_l1,
        w_out, b_out);

    // cell0 -> h1
    lstm_cell_kernel<<<HDIM / 256, 256>>>(p_g0, cell, p_h1, out_h1, out_c1);

    // K2: gates1 += w_ih_l1 @ h1 (67 MB). 4 warps/block for fine granularity.
    k2_l1_ih<<<GDIM / 4, 128>>>(w_ih_l1);

    // cell1 -> h2
    lstm_cell_kernel<<<HDIM / 256, 256>>>(p_g1, cell + HDIM, p_h2, out_h2, out_c2);

    // K3: logits += w_out[:, 1024:] @ h2 (262 MB).
    k3_out_h<<<OUTDIM / 8, 256>>>(w_out);

    // log_softmax
    log_softmax_kernel<<<1, 1024>>>(out_logp);
}